// round 1
// baseline (speedup 1.0000x reference)
#include <cuda_runtime.h>
#include <cstdint>

// Problem constants (fixed shapes)
#define BATCH   4
#define SEQL    4096
#define DMODEL  2048
#define HALF    32
#define N2      64                 // 2*HALF (re || im)
#define MTOT    (BATCH*SEQL)       // 16384
#define CHUNK   64                 // scan chunk length
#define NCHUNK  (SEQL/CHUNK)       // 64 chunks per batch

typedef unsigned long long ull;

// ---------------- scratch (static device globals; no allocation) ----------------
__device__ float g_W1[DMODEL * N2];        // folded B_bar weights [d][j]   (512 KB)
__device__ float g_W2[N2 * DMODEL];        // folded C weights [j][d]       (512 KB)
__device__ float g_Bu[MTOT * N2];          // Bu, then xs in-place          (4 MB)
__device__ float g_carry[BATCH * NCHUNK * N2];
__device__ float g_pref [BATCH * NCHUNK * N2];
// params: [0:32) lb_re, [32:64) lb_im, [64:96) lbS_re, [96:128) lbS_im,
//         [128:160) s_re, [160:192) s_im
__device__ float g_par[192];

// ---------------- f32x2 helpers ----------------
__device__ __forceinline__ ull fma2(ull a, ull b, ull c) {
    ull d;
    asm("fma.rn.f32x2 %0, %1, %2, %3;" : "=l"(d) : "l"(a), "l"(b), "l"(c));
    return d;
}
__device__ __forceinline__ ull pack2(float x) {
    ull d;
    asm("mov.b64 %0, {%1, %1};" : "=l"(d) : "f"(x));
    return d;
}

// ---------------- setup: per-state parameters ----------------
__global__ void k_params(const float* __restrict__ Lur,
                         const float* __restrict__ Lim,
                         const float* __restrict__ logD) {
    int n = threadIdx.x;
    if (n >= HALF) return;
    float x   = Lur[n];
    float sp  = (x > 20.f) ? x : log1pf(expf(x));
    float lre = -(sp + 1e-4f + 0.01f);
    float lim = Lim[n];
    float dt  = expf(logD[n]);
    float ar = lre * dt, ai = lim * dt;
    float er = expf(ar);
    float lbr = er * cosf(ai);
    float lbi = er * sinf(ai);
    // s = (lam_bar - 1) / lam   (complex)
    float den = lre * lre + lim * lim;
    float nr = lbr - 1.f, ni = lbi;
    float sre = (nr * lre + ni * lim) / den;
    float sim = (ni * lre - nr * lim) / den;
    // lam_bar^CHUNK = exp(CHUNK * lam * dt)
    float er64 = expf((float)CHUNK * ar);
    float a64  = (float)CHUNK * ai;
    float lbSr = er64 * cosf(a64);
    float lbSi = er64 * sinf(a64);
    g_par[n]       = lbr;  g_par[32 + n]  = lbi;
    g_par[64 + n]  = lbSr; g_par[96 + n]  = lbSi;
    g_par[128 + n] = sre;  g_par[160 + n] = sim;
}

// W1[d][j]: j<32 -> re part of s*B_tilde;  j>=32 -> im part
__global__ void k_w1(const float* __restrict__ Bre, const float* __restrict__ Bim) {
    for (int idx = blockIdx.x * blockDim.x + threadIdx.x; idx < DMODEL * N2;
         idx += gridDim.x * blockDim.x) {
        int d = idx >> 6;
        int j = idx & 63;
        int n = j & 31;
        float sre = g_par[128 + n], sim = g_par[160 + n];
        float br = Bre[n * DMODEL + d], bi = Bim[n * DMODEL + d];
        g_W1[idx] = (j < 32) ? (sre * br - sim * bi) : (sre * bi + sim * br);
    }
}

// W2[j][d]: j<32 -> 2*C_re[d][j];  j>=32 -> -2*C_im[d][j-32]
__global__ void k_w2(const float* __restrict__ Cre, const float* __restrict__ Cim) {
    for (int idx = blockIdx.x * blockDim.x + threadIdx.x; idx < N2 * DMODEL;
         idx += gridDim.x * blockDim.x) {
        int j = idx >> 11;          // / DMODEL
        int d = idx & 2047;
        g_W2[idx] = (j < 32) ? (2.f * Cre[d * HALF + j])
                             : (-2.f * Cim[d * HALF + (j - 32)]);
    }
}

// ---------------- GEMM1: Bu[m][j] = sum_d u[m][d] * W1[d][j] ----------------
// 128 threads, BM=128, 64 cols, K-tile = 32, TM=8 x TN=8 (f32x2 pairs over cols)
__global__ __launch_bounds__(128) void k_gemm1(const float* __restrict__ u) {
    __shared__ __align__(16) float su[128 * 36];   // [row][k] pad->36
    __shared__ __align__(16) float sw[32 * 64];    // [k][j]
    int tid = threadIdx.x;
    int tx = tid & 7;          // col group (8 cols)
    int ty = tid >> 3;         // 0..15, rows ty + 16*i
    int m0 = blockIdx.x * 128;

    ull acc[8][4];
    #pragma unroll
    for (int i = 0; i < 8; ++i)
        #pragma unroll
        for (int p = 0; p < 4; ++p) acc[i][p] = 0ull;

    for (int kt = 0; kt < DMODEL / 32; ++kt) {
        int kb = kt * 32;
        // u tile: 128 rows x 32 k = 1024 float4, 8 per thread (coalesced)
        #pragma unroll
        for (int t = 0; t < 8; ++t) {
            int idx = tid + 128 * t;
            int ro = idx >> 3, c4 = idx & 7;
            float4 v = *(const float4*)(u + (size_t)(m0 + ro) * DMODEL + kb + c4 * 4);
            *(float4*)(su + ro * 36 + c4 * 4) = v;
        }
        // w tile: 32 x 64 = 512 float4, 4 per thread
        #pragma unroll
        for (int t = 0; t < 4; ++t) {
            int idx = tid + 128 * t;
            int ro = idx >> 4, c4 = idx & 15;
            *(float4*)(sw + ro * 64 + c4 * 4) =
                *(const float4*)(g_W1 + (kb + ro) * 64 + c4 * 4);
        }
        __syncthreads();
        #pragma unroll 8
        for (int k = 0; k < 32; ++k) {
            ull wp[4];
            #pragma unroll
            for (int p = 0; p < 4; ++p)
                wp[p] = *(const ull*)(sw + k * 64 + tx * 8 + 2 * p);
            #pragma unroll
            for (int i = 0; i < 8; ++i) {
                ull up = pack2(su[(ty + 16 * i) * 36 + k]);
                #pragma unroll
                for (int p = 0; p < 4; ++p) acc[i][p] = fma2(wp[p], up, acc[i][p]);
            }
        }
        __syncthreads();
    }
    #pragma unroll
    for (int i = 0; i < 8; ++i) {
        int row = m0 + ty + 16 * i;
        #pragma unroll
        for (int p = 0; p < 4; ++p) {
            float2 f = *reinterpret_cast<float2*>(&acc[i][p]);
            *(float2*)(g_Bu + (size_t)row * N2 + tx * 8 + 2 * p) = f;
        }
    }
}

// ---------------- scan phase 1: per-chunk local recurrence ----------------
// warp per (b, chunk), lane = state n; in-place on g_Bu
__global__ void k_scan_local() {
    int w = (blockIdx.x * blockDim.x + threadIdx.x) >> 5;
    int lane = threadIdx.x & 31;
    int b = w >> 6, c = w & (NCHUNK - 1);
    float lbr = g_par[lane], lbi = g_par[32 + lane];
    float xr = 0.f, xi = 0.f;
    size_t base = ((size_t)b * SEQL + (size_t)c * CHUNK) * N2;
    for (int i = 0; i < CHUNK; ++i) {
        size_t off = base + (size_t)i * N2;
        float br = g_Bu[off + lane];
        float bi = g_Bu[off + 32 + lane];
        float nr = fmaf(lbr, xr, fmaf(-lbi, xi, br));
        float ni = fmaf(lbr, xi, fmaf( lbi, xr, bi));
        g_Bu[off + lane]      = nr;
        g_Bu[off + 32 + lane] = ni;
        xr = nr; xi = ni;
    }
    int co = (b * NCHUNK + c) * N2;
    g_carry[co + lane] = xr;
    g_carry[co + 32 + lane] = xi;
}

// ---------------- scan phase 2: chunk-carry prefix (exclusive) ----------------
__global__ void k_scan_prefix() {
    int w = threadIdx.x >> 5;     // b
    int lane = threadIdx.x & 31;
    float lbSr = g_par[64 + lane], lbSi = g_par[96 + lane];
    float Pr = 0.f, Pi = 0.f;
    for (int c = 0; c < NCHUNK; ++c) {
        int o = (w * NCHUNK + c) * N2;
        g_pref[o + lane] = Pr;
        g_pref[o + 32 + lane] = Pi;
        float cr = g_carry[o + lane];
        float ci = g_carry[o + 32 + lane];
        float nr = fmaf(lbSr, Pr, fmaf(-lbSi, Pi, cr));
        float ni = fmaf(lbSr, Pi, fmaf( lbSi, Pr, ci));
        Pr = nr; Pi = ni;
    }
}

// ---------------- scan phase 3: fixup x[l] += lam^(i+1) * P ----------------
__global__ void k_scan_fix() {
    int w = (blockIdx.x * blockDim.x + threadIdx.x) >> 5;
    int lane = threadIdx.x & 31;
    int b = w >> 6, c = w & (NCHUNK - 1);
    float lbr = g_par[lane], lbi = g_par[32 + lane];
    int po = (b * NCHUNK + c) * N2;
    float Pr = g_pref[po + lane], Pi = g_pref[po + 32 + lane];
    float pr = lbr, pi = lbi;    // lam_bar^(i+1), i = 0
    size_t base = ((size_t)b * SEQL + (size_t)c * CHUNK) * N2;
    for (int i = 0; i < CHUNK; ++i) {
        size_t off = base + (size_t)i * N2;
        float ar = pr * Pr - pi * Pi;
        float ai = pr * Pi + pi * Pr;
        g_Bu[off + lane]      += ar;
        g_Bu[off + 32 + lane] += ai;
        float npr = pr * lbr - pi * lbi;
        float npi = pr * lbi + pi * lbr;
        pr = npr; pi = npi;
    }
}

// ---------------- GEMM2: y[m][d] = X[m][:] @ W2[:,d] + D[d]*u[m][d] ----------------
// 128 threads, BM=128, BN=64, K=64, TM=8 x TN=8 (f32x2 pairs over cols)
__global__ __launch_bounds__(128) void k_gemm2(const float* __restrict__ u,
                                               const float* __restrict__ Dv,
                                               float* __restrict__ y) {
    __shared__ __align__(16) float sx[64 * 128];   // [k][m] transposed
    __shared__ __align__(16) float sw[64 * 64];    // [k][n]
    int tid = threadIdx.x;
    int tx = tid & 7;           // col group
    int ty = tid >> 3;          // 0..15, rows ty + 16*i
    int n0 = blockIdx.x * 64;
    int m0 = blockIdx.y * 128;

    // X tile: thread loads row (m0+tid) fully, scatters transposed (conflict-free STS)
    #pragma unroll
    for (int t = 0; t < 16; ++t) {
        float4 v = *(const float4*)(g_Bu + (size_t)(m0 + tid) * N2 + t * 4);
        sx[(t * 4 + 0) * 128 + tid] = v.x;
        sx[(t * 4 + 1) * 128 + tid] = v.y;
        sx[(t * 4 + 2) * 128 + tid] = v.z;
        sx[(t * 4 + 3) * 128 + tid] = v.w;
    }
    // W2 tile: 64 x 64 = 1024 float4, 8 per thread
    #pragma unroll
    for (int t = 0; t < 8; ++t) {
        int idx = tid + 128 * t;
        int ro = idx >> 4, c4 = idx & 15;
        *(float4*)(sw + ro * 64 + c4 * 4) =
            *(const float4*)(g_W2 + (size_t)ro * DMODEL + n0 + c4 * 4);
    }
    __syncthreads();

    ull acc[8][4];
    #pragma unroll
    for (int i = 0; i < 8; ++i)
        #pragma unroll
        for (int p = 0; p < 4; ++p) acc[i][p] = 0ull;

    #pragma unroll 8
    for (int k = 0; k < 64; ++k) {
        ull wp[4];
        #pragma unroll
        for (int p = 0; p < 4; ++p)
            wp[p] = *(const ull*)(sw + k * 64 + tx * 8 + 2 * p);
        #pragma unroll
        for (int i = 0; i < 8; ++i) {
            ull up = pack2(sx[k * 128 + ty + 16 * i]);
            #pragma unroll
            for (int p = 0; p < 4; ++p) acc[i][p] = fma2(wp[p], up, acc[i][p]);
        }
    }

    // epilogue: + D * u, write y
    float dreg[8];
    #pragma unroll
    for (int cc = 0; cc < 8; ++cc) dreg[cc] = Dv[n0 + tx * 8 + cc];
    #pragma unroll
    for (int i = 0; i < 8; ++i) {
        size_t base = (size_t)(m0 + ty + 16 * i) * DMODEL + n0 + tx * 8;
        #pragma unroll
        for (int p = 0; p < 4; ++p) {
            float2 a = *reinterpret_cast<float2*>(&acc[i][p]);
            float2 uu = *(const float2*)(u + base + 2 * p);
            a.x += dreg[2 * p]     * uu.x;
            a.y += dreg[2 * p + 1] * uu.y;
            *(float2*)(y + base + 2 * p) = a;
        }
    }
}

// ---------------- launch ----------------
extern "C" void kernel_launch(void* const* d_in, const int* in_sizes, int n_in,
                              void* d_out, int out_size) {
    const float* u    = (const float*)d_in[0];
    const float* Lur  = (const float*)d_in[1];
    const float* Lim  = (const float*)d_in[2];
    const float* Bre  = (const float*)d_in[3];
    const float* Bim  = (const float*)d_in[4];
    const float* Cre  = (const float*)d_in[5];
    const float* Cim  = (const float*)d_in[6];
    const float* Dv   = (const float*)d_in[7];
    const float* logD = (const float*)d_in[8];
    float* y = (float*)d_out;

    k_params<<<1, 32>>>(Lur, Lim, logD);
    k_w1<<<128, 256>>>(Bre, Bim);
    k_w2<<<128, 256>>>(Cre, Cim);
    k_gemm1<<<MTOT / 128, 128>>>(u);
    k_scan_local<<<(BATCH * NCHUNK) / 4, 128>>>();
    k_scan_prefix<<<1, BATCH * 32>>>();
    k_scan_fix<<<(BATCH * NCHUNK) / 4, 128>>>();
    k_gemm2<<<dim3(DMODEL / 64, MTOT / 128), 128>>>(u, Dv, y);
}